// round 7
// baseline (speedup 1.0000x reference)
#include <cuda_runtime.h>
#include <cuda_bf16.h>
#include <cstdint>

#define M_ 16384
#define N_ 3072
#define K_ 1024

// -------- device scratch (allowed: __device__ globals) --------
__device__ float g_qkv[(size_t)M_ * N_];               // 192 MB
__device__ __nv_bfloat16 g_Ah[(size_t)M_ * K_];        // 32 MB  x hi   [M,K]
__device__ __nv_bfloat16 g_Al[(size_t)M_ * K_];        // 32 MB  x lo   [M,K]
__device__ __nv_bfloat16 g_Bh[(size_t)N_ * K_];        // 6 MB   W^T hi [N,K]
__device__ __nv_bfloat16 g_Bl[(size_t)N_ * K_];        // 6 MB   W^T lo [N,K]

// ---------------------------------------------------------------------------
// Pre-kernel 1: split x -> bf16 hi/lo, same [M,K] layout.
// ---------------------------------------------------------------------------
__global__ __launch_bounds__(256) void split_x_kernel(const float* __restrict__ x)
{
    size_t idx = (size_t)blockIdx.x * 256 + threadIdx.x;    // float4 index
    float4 v = ((const float4*)x)[idx];
    __nv_bfloat16 hx = __float2bfloat16(v.x);
    __nv_bfloat16 hy = __float2bfloat16(v.y);
    __nv_bfloat16 hz = __float2bfloat16(v.z);
    __nv_bfloat16 hw = __float2bfloat16(v.w);
    __nv_bfloat16 lx = __float2bfloat16(v.x - __bfloat162float(hx));
    __nv_bfloat16 ly = __float2bfloat16(v.y - __bfloat162float(hy));
    __nv_bfloat16 lz = __float2bfloat16(v.z - __bfloat162float(hz));
    __nv_bfloat16 lw = __float2bfloat16(v.w - __bfloat162float(hw));
    __nv_bfloat162 h01; h01.x = hx; h01.y = hy;
    __nv_bfloat162 h23; h23.x = hz; h23.y = hw;
    __nv_bfloat162 l01; l01.x = lx; l01.y = ly;
    __nv_bfloat162 l23; l23.x = lz; l23.y = lw;
    ((__nv_bfloat162*)g_Ah)[2 * idx]     = h01;
    ((__nv_bfloat162*)g_Ah)[2 * idx + 1] = h23;
    ((__nv_bfloat162*)g_Al)[2 * idx]     = l01;
    ((__nv_bfloat162*)g_Al)[2 * idx + 1] = l23;
}

// ---------------------------------------------------------------------------
// Pre-kernel 2: transpose + split W [K,N] -> g_Bh/g_Bl bf16 [N,K].
// ---------------------------------------------------------------------------
__global__ __launch_bounds__(256) void split_w_kernel(const float* __restrict__ W)
{
    __shared__ float t[32][33];
    const int k0 = blockIdx.x * 32;
    const int n0 = blockIdx.y * 32;
    const int tid = threadIdx.x;
    #pragma unroll
    for (int i = 0; i < 4; i++) {
        int idx = tid + i * 256;
        int r = idx >> 5, c = idx & 31;
        t[r][c] = W[(size_t)(k0 + r) * N_ + n0 + c];
    }
    __syncthreads();
    #pragma unroll
    for (int i = 0; i < 4; i++) {
        int idx = tid + i * 256;
        int r = idx >> 5, c = idx & 31;
        float v = t[c][r];
        __nv_bfloat16 hi = __float2bfloat16(v);
        __nv_bfloat16 lo = __float2bfloat16(v - __bfloat162float(hi));
        size_t o = (size_t)(n0 + r) * K_ + k0 + c;
        g_Bh[o] = hi;
        g_Bl[o] = lo;
    }
}

// ---------------------------------------------------------------------------
// Main GEMM: qkv = x @ W + b via mma.sync.m16n8k16 bf16, 3-pass split.
// CTA 128x128, 8 warps (2x4), warp tile 64x32, KC=32.
// 3-stage cp.async ring, ONE __syncthreads per chunk, prefetch distance 2.
// smem rows padded to 40 bf16 (80B) -> conflict-free ldmatrix.
// ---------------------------------------------------------------------------
#define KC 32
#define ASTRIDE 40
#define ROWB (ASTRIDE * 2)                 // 80 bytes per smem row
#define TILE_BYTES (128 * ROWB)            // 10240
#define STG_BYTES (4 * TILE_BYTES)         // Ah, Al, Bh, Bl
#define NSTG 3
#define SMEM_TOTAL (NSTG * STG_BYTES)      // 122880

__device__ __forceinline__ uint32_t cvta_smem(const void* p) {
    uint32_t a;
    asm("{ .reg .u64 t; cvta.to.shared.u64 t, %1; cvt.u32.u64 %0, t; }"
        : "=r"(a) : "l"(p));
    return a;
}

#define CP16(dst, src) \
    asm volatile("cp.async.cg.shared.global [%0], [%1], 16;" \
                 :: "r"(dst), "l"(src) : "memory")

#define LDSM4(r, addr) \
    asm volatile("ldmatrix.sync.aligned.m8n8.x4.shared.b16 {%0,%1,%2,%3}, [%4];" \
                 : "=r"((r)[0]), "=r"((r)[1]), "=r"((r)[2]), "=r"((r)[3]) \
                 : "r"(addr))

#define MMA16816(c, a, b0, b1) \
    asm volatile("mma.sync.aligned.m16n8k16.row.col.f32.bf16.bf16.f32 " \
                 "{%0,%1,%2,%3}, {%4,%5,%6,%7}, {%8,%9}, {%0,%1,%2,%3};" \
                 : "+f"((c)[0]), "+f"((c)[1]), "+f"((c)[2]), "+f"((c)[3]) \
                 : "r"((a)[0]), "r"((a)[1]), "r"((a)[2]), "r"((a)[3]), \
                   "r"(b0), "r"(b1))

__global__ __launch_bounds__(256) void gemm_bf16_kernel(const float* __restrict__ bias)
{
    extern __shared__ __align__(128) char smem[];
    const uint32_t sb = cvta_smem(smem);

    const int tid  = threadIdx.x;
    const int wid  = tid >> 5;
    const int lane = tid & 31;
    const int wm   = wid >> 2;          // 0..1 (M)
    const int wn   = wid & 3;           // 0..3 (N)
    const int n0 = blockIdx.x * 128;
    const int m0 = blockIdx.y * 128;

    // per-thread cp.async coordinates: 2 x (row, 16B col) per matrix
    const int r0 = tid >> 2;            // rows 0..63
    const int r1 = r0 + 64;             // rows 64..127
    const int c16 = (tid & 3) * 16;     // byte offset within 64B row payload

    float acc[4][4][4];
    #pragma unroll
    for (int i = 0; i < 4; i++)
        #pragma unroll
        for (int j = 0; j < 4; j++)
            #pragma unroll
            for (int q = 0; q < 4; q++) acc[i][j][q] = 0.0f;

    #define LOAD_STAGE(s, c)  do {                                              \
        uint32_t db = sb + (s) * STG_BYTES;                                     \
        int k0 = (c) * KC;                                                      \
        const char* ah0 = (const char*)(g_Ah + (size_t)(m0 + r0) * K_ + k0) + c16; \
        const char* ah1 = (const char*)(g_Ah + (size_t)(m0 + r1) * K_ + k0) + c16; \
        const char* al0 = (const char*)(g_Al + (size_t)(m0 + r0) * K_ + k0) + c16; \
        const char* al1 = (const char*)(g_Al + (size_t)(m0 + r1) * K_ + k0) + c16; \
        const char* bh0 = (const char*)(g_Bh + (size_t)(n0 + r0) * K_ + k0) + c16; \
        const char* bh1 = (const char*)(g_Bh + (size_t)(n0 + r1) * K_ + k0) + c16; \
        const char* bl0 = (const char*)(g_Bl + (size_t)(n0 + r0) * K_ + k0) + c16; \
        const char* bl1 = (const char*)(g_Bl + (size_t)(n0 + r1) * K_ + k0) + c16; \
        uint32_t d0 = db + r0 * ROWB + c16;                                     \
        uint32_t d1 = db + r1 * ROWB + c16;                                     \
        CP16(d0, ah0);                      CP16(d1, ah1);                      \
        CP16(d0 + TILE_BYTES, al0);         CP16(d1 + TILE_BYTES, al1);         \
        CP16(d0 + 2 * TILE_BYTES, bh0);     CP16(d1 + 2 * TILE_BYTES, bh1);     \
        CP16(d0 + 3 * TILE_BYTES, bl0);     CP16(d1 + 3 * TILE_BYTES, bl1);     \
        asm volatile("cp.async.commit_group;" ::: "memory");                    \
    } while (0)

    // prologue: stages 0 and 1 in flight
    LOAD_STAGE(0, 0);
    LOAD_STAGE(1, 1);

    // ldmatrix lane addressing (constant across chunks)
    const int rA = wm * 64 + ((lane >> 3) & 1) * 8 + (lane & 7);
    const int cA = ((lane >> 4) & 1) * 8;                  // + kk*16
    const int rB = wn * 32 + ((lane >> 4) & 1) * 8 + (lane & 7);
    const int cB = ((lane >> 3) & 1) * 8;                  // + kk*16

    const int NCH = K_ / KC;
    int stage = 0;
    for (int c = 0; c < NCH; c++) {
        // chunk c's group has arrived once <=1 group remains outstanding
        if (c + 1 < NCH)
            asm volatile("cp.async.wait_group 1;" ::: "memory");
        else
            asm volatile("cp.async.wait_group 0;" ::: "memory");
        __syncthreads();   // data visible to all; all warps done with stage (c-1)%3

        // prefetch chunk c+2 into stage (c+2)%3 == (c-1)%3 (freed by the barrier)
        if (c + 2 < NCH) {
            int ps = stage + 2; if (ps >= NSTG) ps -= NSTG;
            LOAD_STAGE(ps, c + 2);
        }

        const uint32_t st = sb + stage * STG_BYTES;
        #pragma unroll
        for (int kk = 0; kk < 2; kk++) {
            uint32_t a_h[4][4], a_l[4][4], b_h[2][4], b_l[2][4];
            #pragma unroll
            for (int mi = 0; mi < 4; mi++) {
                uint32_t ad = st + (rA + mi * 16) * ROWB + (cA + kk * 16) * 2;
                LDSM4(a_h[mi], ad);
                LDSM4(a_l[mi], ad + TILE_BYTES);
            }
            #pragma unroll
            for (int ni = 0; ni < 2; ni++) {
                uint32_t bd = st + 2 * TILE_BYTES +
                              (rB + ni * 16) * ROWB + (cB + kk * 16) * 2;
                LDSM4(b_h[ni], bd);
                LDSM4(b_l[ni], bd + TILE_BYTES);
            }
            // pass 1: Ah * Bh
            #pragma unroll
            for (int mi = 0; mi < 4; mi++)
                #pragma unroll
                for (int nj = 0; nj < 4; nj++)
                    MMA16816(acc[mi][nj], a_h[mi],
                             b_h[nj >> 1][(nj & 1) * 2], b_h[nj >> 1][(nj & 1) * 2 + 1]);
            // pass 2: Ah * Bl
            #pragma unroll
            for (int mi = 0; mi < 4; mi++)
                #pragma unroll
                for (int nj = 0; nj < 4; nj++)
                    MMA16816(acc[mi][nj], a_h[mi],
                             b_l[nj >> 1][(nj & 1) * 2], b_l[nj >> 1][(nj & 1) * 2 + 1]);
            // pass 3: Al * Bh
            #pragma unroll
            for (int mi = 0; mi < 4; mi++)
                #pragma unroll
                for (int nj = 0; nj < 4; nj++)
                    MMA16816(acc[mi][nj], a_l[mi],
                             b_h[nj >> 1][(nj & 1) * 2], b_h[nj >> 1][(nj & 1) * 2 + 1]);
        }
        stage++; if (stage >= NSTG) stage -= NSTG;
    }

    // ---- epilogue: bias + store f32 ----
    #pragma unroll
    for (int mi = 0; mi < 4; mi++) {
        #pragma unroll
        for (int nj = 0; nj < 4; nj++) {
            int row = m0 + wm * 64 + mi * 16 + (lane >> 2);
            int col = n0 + wn * 32 + nj * 8 + (lane & 3) * 2;
            float2 bv = *(const float2*)(bias + col);
            float2 v0, v1;
            v0.x = acc[mi][nj][0] + bv.x;
            v0.y = acc[mi][nj][1] + bv.y;
            v1.x = acc[mi][nj][2] + bv.x;
            v1.y = acc[mi][nj][3] + bv.y;
            *(float2*)(g_qkv + (size_t)row * N_ + col)       = v0;
            *(float2*)(g_qkv + (size_t)(row + 8) * N_ + col) = v1;
        }
    }
}

// ---------------------------------------------------------------------------
// Attention kernel. Padded per-head stride 196 floats; float4-vectorized
// score dot and V pass (LDS.128 instead of LDS.32, E reads broadcast).
// ---------------------------------------------------------------------------
#define HSTR 196                         // padded per-head stride (floats)
#define HSTR4 49                         // float4 stride

__global__ __launch_bounds__(256, 4) void attn_kernel(float* __restrict__ out)
{
    __shared__ __align__(16) float qkv[16 * HSTR];   // 12.25 KB
    __shared__ float E[256];
    __shared__ float invden[16];

    const int token = blockIdx.x;
    const int tid   = threadIdx.x;

    // Stage token row (768 float4) into padded layout: 48 float4 per head.
    const float4* row4 = (const float4*)(g_qkv + (size_t)token * N_);
    #pragma unroll
    for (int r = 0; r < 3; r++) {
        int i = tid + r * 256;
        int head = i / 48;
        int w    = i - head * 48;
        ((float4*)qkv)[head * HSTR4 + w] = row4[i];
    }
    __syncthreads();

    // Scores: one (h,g) per thread; float4 dot (both bases 16B-aligned).
    const int h = tid >> 4;
    const int g = tid & 15;
    const float4* qp = (const float4*)&qkv[h * HSTR];        // h*784 bytes
    const float4* kp = (const float4*)&qkv[g * HSTR + 64];   // +256 bytes
    float s = 0.0f;
    #pragma unroll
    for (int d = 0; d < 16; d++) {
        float4 q4 = qp[d];
        float4 k4 = kp[d];
        s = fmaf(q4.x, k4.x, s);
        s = fmaf(q4.y, k4.y, s);
        s = fmaf(q4.z, k4.z, s);
        s = fmaf(q4.w, k4.w, s);
    }
    s -= 20.0f;
    E[tid] = (s > 20.0f || s < -20.0f) ? 0.0f : expf(s);
    __syncthreads();

    if (tid < 16) {
        float den = 0.0f;
        #pragma unroll
        for (int gg = 0; gg < 16; gg++) den += E[tid * 16 + gg];
        invden[tid] = 1.0f / den;
    }
    __syncthreads();

    // out[h, d0..d0+3] per thread: 256 threads x float4 = 1024 outputs.
    const int hh = tid >> 4;              // head
    const int d4 = (tid & 15);            // float4 index within head (0..15)
    float4 a = make_float4(0.f, 0.f, 0.f, 0.f);
    const float* Eh = &E[hh * 16];
    #pragma unroll
    for (int gg = 0; gg < 16; gg++) {
        float e = Eh[gg];                                    // broadcast
        float4 v4 = *(const float4*)&qkv[gg * HSTR + 128 + d4 * 4];
        a.x = fmaf(e, v4.x, a.x);
        a.y = fmaf(e, v4.y, a.y);
        a.z = fmaf(e, v4.z, a.z);
        a.w = fmaf(e, v4.w, a.w);
    }
    float inv = invden[hh];
    a.x *= inv; a.y *= inv; a.z *= inv; a.w *= inv;
    ((float4*)(out + (size_t)token * 1024))[tid] = a;
}

// ---------------------------------------------------------------------------
extern "C" void kernel_launch(void* const* d_in, const int* in_sizes, int n_in,
                              void* d_out, int out_size)
{
    const float* x = (const float*)d_in[0];
    const float* W = (const float*)d_in[1];
    const float* b = (const float*)d_in[2];
    float* out = (float*)d_out;

    cudaFuncSetAttribute(gemm_bf16_kernel,
                         cudaFuncAttributeMaxDynamicSharedMemorySize, SMEM_TOTAL);

    split_x_kernel<<<(M_ * K_) / (256 * 4), 256>>>(x);
    split_w_kernel<<<dim3(K_ / 32, N_ / 32), 256>>>(W);
    gemm_bf16_kernel<<<dim3(N_ / 128, M_ / 128), 256, SMEM_TOTAL>>>(b);
    attn_kernel<<<M_, 256>>>(out);
}

// round 8
// speedup vs baseline: 1.0875x; 1.0875x over previous
#include <cuda_runtime.h>
#include <cuda_bf16.h>
#include <cstdint>

#define M_ 16384
#define N_ 3072
#define K_ 1024

// -------- device scratch (allowed: __device__ globals) --------
__device__ float g_qkv[(size_t)M_ * N_];               // 192 MB
__device__ __nv_bfloat16 g_Ah[(size_t)M_ * K_];        // 32 MB  x hi   [M,K]
__device__ __nv_bfloat16 g_Al[(size_t)M_ * K_];        // 32 MB  x lo   [M,K]
__device__ __nv_bfloat16 g_Bh[(size_t)N_ * K_];        // 6 MB   W^T hi [N,K]
__device__ __nv_bfloat16 g_Bl[(size_t)N_ * K_];        // 6 MB   W^T lo [N,K]

// ---------------------------------------------------------------------------
// Pre-kernel 1: split x -> bf16 hi/lo, same [M,K] layout.
// ---------------------------------------------------------------------------
__global__ __launch_bounds__(256) void split_x_kernel(const float* __restrict__ x)
{
    size_t idx = (size_t)blockIdx.x * 256 + threadIdx.x;    // float4 index
    float4 v = ((const float4*)x)[idx];
    __nv_bfloat16 hx = __float2bfloat16(v.x);
    __nv_bfloat16 hy = __float2bfloat16(v.y);
    __nv_bfloat16 hz = __float2bfloat16(v.z);
    __nv_bfloat16 hw = __float2bfloat16(v.w);
    __nv_bfloat16 lx = __float2bfloat16(v.x - __bfloat162float(hx));
    __nv_bfloat16 ly = __float2bfloat16(v.y - __bfloat162float(hy));
    __nv_bfloat16 lz = __float2bfloat16(v.z - __bfloat162float(hz));
    __nv_bfloat16 lw = __float2bfloat16(v.w - __bfloat162float(hw));
    __nv_bfloat162 h01; h01.x = hx; h01.y = hy;
    __nv_bfloat162 h23; h23.x = hz; h23.y = hw;
    __nv_bfloat162 l01; l01.x = lx; l01.y = ly;
    __nv_bfloat162 l23; l23.x = lz; l23.y = lw;
    ((__nv_bfloat162*)g_Ah)[2 * idx]     = h01;
    ((__nv_bfloat162*)g_Ah)[2 * idx + 1] = h23;
    ((__nv_bfloat162*)g_Al)[2 * idx]     = l01;
    ((__nv_bfloat162*)g_Al)[2 * idx + 1] = l23;
}

// ---------------------------------------------------------------------------
// Pre-kernel 2: transpose + split W [K,N] -> g_Bh/g_Bl bf16 [N,K].
// ---------------------------------------------------------------------------
__global__ __launch_bounds__(256) void split_w_kernel(const float* __restrict__ W)
{
    __shared__ float t[32][33];
    const int k0 = blockIdx.x * 32;
    const int n0 = blockIdx.y * 32;
    const int tid = threadIdx.x;
    #pragma unroll
    for (int i = 0; i < 4; i++) {
        int idx = tid + i * 256;
        int r = idx >> 5, c = idx & 31;
        t[r][c] = W[(size_t)(k0 + r) * N_ + n0 + c];
    }
    __syncthreads();
    #pragma unroll
    for (int i = 0; i < 4; i++) {
        int idx = tid + i * 256;
        int r = idx >> 5, c = idx & 31;
        float v = t[c][r];
        __nv_bfloat16 hi = __float2bfloat16(v);
        __nv_bfloat16 lo = __float2bfloat16(v - __bfloat162float(hi));
        size_t o = (size_t)(n0 + r) * K_ + k0 + c;
        g_Bh[o] = hi;
        g_Bl[o] = lo;
    }
}

// ---------------------------------------------------------------------------
// Main GEMM: qkv = x @ W + b via mma.sync.m16n8k16 bf16, 3-pass split.
// CTA 128x128, 8 warps (2x4), warp tile 64x32, KC=32, 2-stage cp.async
// pipeline (R4/R5 structure — best measured). All 24 LDSM for a chunk are
// issued before any MMA for deeper lookahead.
// ---------------------------------------------------------------------------
#define KC 32
#define ASTRIDE 40
#define ROWB (ASTRIDE * 2)                 // 80 bytes per smem row
#define TILE_BYTES (128 * ROWB)            // 10240
#define STG_BYTES (4 * TILE_BYTES)         // Ah, Al, Bh, Bl
#define SMEM_TOTAL (2 * STG_BYTES)         // 81920

__device__ __forceinline__ uint32_t cvta_smem(const void* p) {
    uint32_t a;
    asm("{ .reg .u64 t; cvta.to.shared.u64 t, %1; cvt.u32.u64 %0, t; }"
        : "=r"(a) : "l"(p));
    return a;
}

#define CP16(dst, src) \
    asm volatile("cp.async.cg.shared.global [%0], [%1], 16;" \
                 :: "r"(dst), "l"(src) : "memory")

#define LDSM4(r, addr) \
    asm volatile("ldmatrix.sync.aligned.m8n8.x4.shared.b16 {%0,%1,%2,%3}, [%4];" \
                 : "=r"((r)[0]), "=r"((r)[1]), "=r"((r)[2]), "=r"((r)[3]) \
                 : "r"(addr))

#define MMA16816(c, a, b0, b1) \
    asm volatile("mma.sync.aligned.m16n8k16.row.col.f32.bf16.bf16.f32 " \
                 "{%0,%1,%2,%3}, {%4,%5,%6,%7}, {%8,%9}, {%0,%1,%2,%3};" \
                 : "+f"((c)[0]), "+f"((c)[1]), "+f"((c)[2]), "+f"((c)[3]) \
                 : "r"((a)[0]), "r"((a)[1]), "r"((a)[2]), "r"((a)[3]), \
                   "r"(b0), "r"(b1))

__global__ __launch_bounds__(256) void gemm_bf16_kernel(const float* __restrict__ bias)
{
    extern __shared__ __align__(128) char smem[];
    const uint32_t sb = cvta_smem(smem);

    const int tid  = threadIdx.x;
    const int wid  = tid >> 5;
    const int lane = tid & 31;
    const int wm   = wid >> 2;          // 0..1 (M)
    const int wn   = wid & 3;           // 0..3 (N)
    const int n0 = blockIdx.x * 128;
    const int m0 = blockIdx.y * 128;

    // per-thread cp.async coordinates: 2 x (row, 16B col) per matrix
    const int r0 = tid >> 2;            // rows 0..63
    const int r1 = r0 + 64;             // rows 64..127
    const int c16 = (tid & 3) * 16;     // byte offset within 64B row payload

    float acc[4][4][4];
    #pragma unroll
    for (int i = 0; i < 4; i++)
        #pragma unroll
        for (int j = 0; j < 4; j++)
            #pragma unroll
            for (int q = 0; q < 4; q++) acc[i][j][q] = 0.0f;

    #define LOAD_STAGE(s, c)  do {                                              \
        uint32_t db = sb + (s) * STG_BYTES;                                     \
        int k0 = (c) * KC;                                                      \
        const char* ah0 = (const char*)(g_Ah + (size_t)(m0 + r0) * K_ + k0) + c16; \
        const char* ah1 = (const char*)(g_Ah + (size_t)(m0 + r1) * K_ + k0) + c16; \
        const char* al0 = (const char*)(g_Al + (size_t)(m0 + r0) * K_ + k0) + c16; \
        const char* al1 = (const char*)(g_Al + (size_t)(m0 + r1) * K_ + k0) + c16; \
        const char* bh0 = (const char*)(g_Bh + (size_t)(n0 + r0) * K_ + k0) + c16; \
        const char* bh1 = (const char*)(g_Bh + (size_t)(n0 + r1) * K_ + k0) + c16; \
        const char* bl0 = (const char*)(g_Bl + (size_t)(n0 + r0) * K_ + k0) + c16; \
        const char* bl1 = (const char*)(g_Bl + (size_t)(n0 + r1) * K_ + k0) + c16; \
        uint32_t d0 = db + r0 * ROWB + c16;                                     \
        uint32_t d1 = db + r1 * ROWB + c16;                                     \
        CP16(d0, ah0);                      CP16(d1, ah1);                      \
        CP16(d0 + TILE_BYTES, al0);         CP16(d1 + TILE_BYTES, al1);         \
        CP16(d0 + 2 * TILE_BYTES, bh0);     CP16(d1 + 2 * TILE_BYTES, bh1);     \
        CP16(d0 + 3 * TILE_BYTES, bl0);     CP16(d1 + 3 * TILE_BYTES, bl1);     \
        asm volatile("cp.async.commit_group;" ::: "memory");                    \
    } while (0)

    LOAD_STAGE(0, 0);

    // ldmatrix lane addressing (constant across chunks)
    const int rA = wm * 64 + ((lane >> 3) & 1) * 8 + (lane & 7);
    const int cA = ((lane >> 4) & 1) * 8;                  // + kk*16
    const int rB = wn * 32 + ((lane >> 4) & 1) * 8 + (lane & 7);
    const int cB = ((lane >> 3) & 1) * 8;                  // + kk*16

    const int NCH = K_ / KC;
    for (int c = 0; c < NCH; c++) {
        if (c + 1 < NCH) {
            LOAD_STAGE((c + 1) & 1, c + 1);
            asm volatile("cp.async.wait_group 1;" ::: "memory");
        } else {
            asm volatile("cp.async.wait_group 0;" ::: "memory");
        }
        __syncthreads();

        const uint32_t st = sb + (c & 1) * STG_BYTES;

        // ---- load ALL fragments for both kk halves up front ----
        uint32_t a_h[2][4][4], a_l[2][4][4], b_h[2][2][4], b_l[2][2][4];
        #pragma unroll
        for (int kk = 0; kk < 2; kk++) {
            #pragma unroll
            for (int mi = 0; mi < 4; mi++) {
                uint32_t ad = st + (rA + mi * 16) * ROWB + (cA + kk * 16) * 2;
                LDSM4(a_h[kk][mi], ad);
                LDSM4(a_l[kk][mi], ad + TILE_BYTES);
            }
            #pragma unroll
            for (int ni = 0; ni < 2; ni++) {
                uint32_t bd = st + 2 * TILE_BYTES +
                              (rB + ni * 16) * ROWB + (cB + kk * 16) * 2;
                LDSM4(b_h[kk][ni], bd);
                LDSM4(b_l[kk][ni], bd + TILE_BYTES);
            }
        }

        // ---- MMAs ----
        #pragma unroll
        for (int kk = 0; kk < 2; kk++) {
            // pass 1: Ah * Bh
            #pragma unroll
            for (int mi = 0; mi < 4; mi++)
                #pragma unroll
                for (int nj = 0; nj < 4; nj++)
                    MMA16816(acc[mi][nj], a_h[kk][mi],
                             b_h[kk][nj >> 1][(nj & 1) * 2],
                             b_h[kk][nj >> 1][(nj & 1) * 2 + 1]);
            // pass 2: Ah * Bl
            #pragma unroll
            for (int mi = 0; mi < 4; mi++)
                #pragma unroll
                for (int nj = 0; nj < 4; nj++)
                    MMA16816(acc[mi][nj], a_h[kk][mi],
                             b_l[kk][nj >> 1][(nj & 1) * 2],
                             b_l[kk][nj >> 1][(nj & 1) * 2 + 1]);
            // pass 3: Al * Bh
            #pragma unroll
            for (int mi = 0; mi < 4; mi++)
                #pragma unroll
                for (int nj = 0; nj < 4; nj++)
                    MMA16816(acc[mi][nj], a_l[kk][mi],
                             b_h[kk][nj >> 1][(nj & 1) * 2],
                             b_h[kk][nj >> 1][(nj & 1) * 2 + 1]);
        }
        __syncthreads();
    }

    // ---- epilogue: bias + store f32 ----
    #pragma unroll
    for (int mi = 0; mi < 4; mi++) {
        #pragma unroll
        for (int nj = 0; nj < 4; nj++) {
            int row = m0 + wm * 64 + mi * 16 + (lane >> 2);
            int col = n0 + wn * 32 + nj * 8 + (lane & 3) * 2;
            float2 bv = *(const float2*)(bias + col);
            float2 v0, v1;
            v0.x = acc[mi][nj][0] + bv.x;
            v0.y = acc[mi][nj][1] + bv.y;
            v1.x = acc[mi][nj][2] + bv.x;
            v1.y = acc[mi][nj][3] + bv.y;
            *(float2*)(g_qkv + (size_t)row * N_ + col)       = v0;
            *(float2*)(g_qkv + (size_t)(row + 8) * N_ + col) = v1;
        }
    }
}

// ---------------------------------------------------------------------------
// Attention kernel. Padded per-head stride 196 floats; float4 loads with
// RESTORED ILP: 8 independent FMA chains in the score dot (2 float4 accs),
// 2 independent float4 accumulators in the V pass.
// ---------------------------------------------------------------------------
#define HSTR 196                         // padded per-head stride (floats)
#define HSTR4 49                         // float4 stride

__global__ __launch_bounds__(256, 4) void attn_kernel(float* __restrict__ out)
{
    __shared__ __align__(16) float qkv[16 * HSTR];   // 12.25 KB
    __shared__ float E[256];
    __shared__ float invden[16];

    const int token = blockIdx.x;
    const int tid   = threadIdx.x;

    // Stage token row (768 float4) into padded layout: 48 float4 per head.
    const float4* row4 = (const float4*)(g_qkv + (size_t)token * N_);
    #pragma unroll
    for (int r = 0; r < 3; r++) {
        int i = tid + r * 256;
        int head = i / 48;
        int w    = i - head * 48;
        ((float4*)qkv)[head * HSTR4 + w] = row4[i];
    }
    __syncthreads();

    // Scores: one (h,g) per thread; float4 dot, 8 independent chains.
    const int h = tid >> 4;
    const int g = tid & 15;
    const float4* qp = (const float4*)&qkv[h * HSTR];
    const float4* kp = (const float4*)&qkv[g * HSTR + 64];
    float4 s0 = make_float4(0.f, 0.f, 0.f, 0.f);
    float4 s1 = make_float4(0.f, 0.f, 0.f, 0.f);
    #pragma unroll
    for (int d = 0; d < 16; d += 2) {
        float4 q0 = qp[d],     k0 = kp[d];
        float4 q1 = qp[d + 1], k1 = kp[d + 1];
        s0.x = fmaf(q0.x, k0.x, s0.x);
        s0.y = fmaf(q0.y, k0.y, s0.y);
        s0.z = fmaf(q0.z, k0.z, s0.z);
        s0.w = fmaf(q0.w, k0.w, s0.w);
        s1.x = fmaf(q1.x, k1.x, s1.x);
        s1.y = fmaf(q1.y, k1.y, s1.y);
        s1.z = fmaf(q1.z, k1.z, s1.z);
        s1.w = fmaf(q1.w, k1.w, s1.w);
    }
    float s = ((s0.x + s1.x) + (s0.y + s1.y)) + ((s0.z + s1.z) + (s0.w + s1.w));
    s -= 20.0f;
    E[tid] = (s > 20.0f || s < -20.0f) ? 0.0f : expf(s);
    __syncthreads();

    if (tid < 16) {
        float den = 0.0f;
        #pragma unroll
        for (int gg = 0; gg < 16; gg++) den += E[tid * 16 + gg];
        invden[tid] = 1.0f / den;
    }
    __syncthreads();

    // out[h, 4d..4d+3] per thread; two independent accumulators over g.
    const int hh = tid >> 4;
    const int d4 = tid & 15;
    float4 a0 = make_float4(0.f, 0.f, 0.f, 0.f);
    float4 a1 = make_float4(0.f, 0.f, 0.f, 0.f);
    const float* Eh = &E[hh * 16];
    #pragma unroll
    for (int gg = 0; gg < 8; gg++) {
        float e0 = Eh[gg];
        float e1 = Eh[gg + 8];
        float4 v0 = *(const float4*)&qkv[gg * HSTR + 128 + d4 * 4];
        float4 v1 = *(const float4*)&qkv[(gg + 8) * HSTR + 128 + d4 * 4];
        a0.x = fmaf(e0, v0.x, a0.x);
        a0.y = fmaf(e0, v0.y, a0.y);
        a0.z = fmaf(e0, v0.z, a0.z);
        a0.w = fmaf(e0, v0.w, a0.w);
        a1.x = fmaf(e1, v1.x, a1.x);
        a1.y = fmaf(e1, v1.y, a1.y);
        a1.z = fmaf(e1, v1.z, a1.z);
        a1.w = fmaf(e1, v1.w, a1.w);
    }
    float inv = invden[hh];
    float4 a;
    a.x = (a0.x + a1.x) * inv;
    a.y = (a0.y + a1.y) * inv;
    a.z = (a0.z + a1.z) * inv;
    a.w = (a0.w + a1.w) * inv;
    ((float4*)(out + (size_t)token * 1024))[tid] = a;
}

// ---------------------------------------------------------------------------
extern "C" void kernel_launch(void* const* d_in, const int* in_sizes, int n_in,
                              void* d_out, int out_size)
{
    const float* x = (const float*)d_in[0];
    const float* W = (const float*)d_in[1];
    const float* b = (const float*)d_in[2];
    float* out = (float*)d_out;

    cudaFuncSetAttribute(gemm_bf16_kernel,
                         cudaFuncAttributeMaxDynamicSharedMemorySize, SMEM_TOTAL);

    split_x_kernel<<<(M_ * K_) / (256 * 4), 256>>>(x);
    split_w_kernel<<<dim3(K_ / 32, N_ / 32), 256>>>(W);
    gemm_bf16_kernel<<<dim3(N_ / 128, M_ / 128), 256, SMEM_TOTAL>>>(b);
    attn_kernel<<<M_, 256>>>(out);
}